// round 1
// baseline (speedup 1.0000x reference)
#include <cuda_runtime.h>

// ---------------- problem constants (fixed by setup_inputs) ----------------
#define TOTAL   32768          // B*N nodes
#define BGRAPH  16
#define NPG     2048           // nodes per graph
#define CDIM    16
#define ODIM    64
#define KNN     16
#define NEDGE   (TOTAL*KNN)    // 524288
#define RBLOCKS 512
#define RTHREADS 256
#define NWARPS_TOT (RBLOCKS*(RTHREADS/32))   // 4096 warps -> 8 nodes/warp

// ---------------- device scratch (static, allocation-free) -----------------
__device__ float g_u[TOTAL*ODIM];
__device__ float g_v[TOTAL*ODIM];
__device__ int   g_idx[NEDGE];
__device__ float g_gt[NEDGE];
__device__ float g_p1[RBLOCKS*ODIM];
__device__ float g_p2[RBLOCKS*ODIM];
__device__ float g_gp1[RBLOCKS];
__device__ float g_gp2[RBLOCKS];
__device__ float g_bnA[ODIM];
__device__ float g_bnB[ODIM];
__device__ float g_gAB[2];

__device__ __forceinline__ float silu_f(float z) {
    return z / (1.0f + __expf(-z));
}

// ---------------- kNN: thread-per-query, buffered replace-max top-16 -------
__device__ __forceinline__ void knn_flush(float (&bk)[KNN], int (&bjv)[KNN],
                                          float &cmax, int &cnt,
                                          const unsigned long long* sbuf) {
    unsigned mx = __reduce_max_sync(0xffffffffu, (unsigned)cnt);
    for (unsigned t = 0; t < mx; ++t) {
        bool act = (t < (unsigned)cnt);
        unsigned long long pk = act ? sbuf[t*256u + threadIdx.x] : 0ull;
        float key = __uint_as_float((unsigned)(pk >> 32));
        int jj = (int)(pk & 0xffffffffu);
        if (act && key < cmax) {
            int pmax = 0; float vmax = bk[0];
#pragma unroll
            for (int p = 1; p < KNN; ++p) { if (bk[p] > vmax) { vmax = bk[p]; pmax = p; } }
#pragma unroll
            for (int p = 0; p < KNN; ++p) { if (p == pmax) { bk[p] = key; bjv[p] = jj; } }
            cmax = bk[0];
#pragma unroll
            for (int p = 1; p < KNN; ++p) cmax = fmaxf(cmax, bk[p]);
        }
    }
    cnt = 0;
}

__global__ void __launch_bounds__(256, 1) knn_kernel(const float* __restrict__ x) {
    extern __shared__ unsigned char smraw[];
    float4* sp4 = (float4*)smraw;                                   // 2048*4 float4 (131072 B)
    float*  ssq = (float*)(smraw + NPG*CDIM*4);                     // 2048 floats (8192 B)
    unsigned long long* sbuf =
        (unsigned long long*)(smraw + NPG*CDIM*4 + NPG*4);          // 16*256 u64 (32768 B)

    int g = blockIdx.x >> 3;   // 8 blocks per graph
    const float* xg = x + (size_t)g * (NPG*CDIM);

    for (int t = threadIdx.x; t < NPG; t += 256) {
        const float4* p = (const float4*)(xg + t*CDIM);
        float4 f0 = p[0], f1 = p[1], f2 = p[2], f3 = p[3];
        sp4[t*4+0] = f0; sp4[t*4+1] = f1; sp4[t*4+2] = f2; sp4[t*4+3] = f3;
        float sq = f0.x*f0.x + f0.y*f0.y + f0.z*f0.z + f0.w*f0.w
                 + f1.x*f1.x + f1.y*f1.y + f1.z*f1.z + f1.w*f1.w
                 + f2.x*f2.x + f2.y*f2.y + f2.z*f2.z + f2.w*f2.w
                 + f3.x*f3.x + f3.y*f3.y + f3.z*f3.z + f3.w*f3.w;
        ssq[t] = sq;
    }
    __syncthreads();

    int qloc = ((blockIdx.x & 7) << 8) + threadIdx.x;
    float xq[16];
    ((float4*)xq)[0] = sp4[qloc*4+0];
    ((float4*)xq)[1] = sp4[qloc*4+1];
    ((float4*)xq)[2] = sp4[qloc*4+2];
    ((float4*)xq)[3] = sp4[qloc*4+3];
#pragma unroll
    for (int c = 0; c < 16; ++c) xq[c] *= -2.0f;   // key = sq_j - 2*dot

    float bk[KNN]; int bjv[KNN];
#pragma unroll
    for (int p = 0; p < KNN; ++p) { bk[p] = __int_as_float(0x7f800000); bjv[p] = 0; }
    float cmax = __int_as_float(0x7f800000);
    int cnt = 0;

    for (int j = 0; j < NPG; ++j) {
        float4 c0 = sp4[j*4+0], c1 = sp4[j*4+1], c2 = sp4[j*4+2], c3 = sp4[j*4+3];
        float k0 = ssq[j];
        k0 = fmaf(xq[0],  c0.x, k0); k0 = fmaf(xq[1],  c0.y, k0);
        k0 = fmaf(xq[2],  c0.z, k0); k0 = fmaf(xq[3],  c0.w, k0);
        float k1 =        xq[4]*c1.x;
        k1 = fmaf(xq[5],  c1.y, k1); k1 = fmaf(xq[6],  c1.z, k1); k1 = fmaf(xq[7],  c1.w, k1);
        float k2 =        xq[8]*c2.x;
        k2 = fmaf(xq[9],  c2.y, k2); k2 = fmaf(xq[10], c2.z, k2); k2 = fmaf(xq[11], c2.w, k2);
        float k3 =        xq[12]*c3.x;
        k3 = fmaf(xq[13], c3.y, k3); k3 = fmaf(xq[14], c3.z, k3); k3 = fmaf(xq[15], c3.w, k3);
        float key = (k0 + k1) + (k2 + k3);

        if (key < cmax) {
            sbuf[(unsigned)cnt*256u + threadIdx.x] =
                (((unsigned long long)__float_as_uint(key)) << 32) | (unsigned)j;
            ++cnt;
        }
        if (__any_sync(0xffffffffu, cnt == KNN)) {
            knn_flush(bk, bjv, cmax, cnt, sbuf);
        }
    }
    knn_flush(bk, bjv, cmax, cnt, sbuf);

    int base = (g*NPG + qloc) * KNN;
    int goff = g * NPG;
#pragma unroll
    for (int p = 0; p < KNN; ++p) g_idx[base + p] = goff + bjv[p];
}

// ---------------- u/v per node: h_edge = u_i + v_j -------------------------
__global__ void uv_kernel(const float* __restrict__ x,
                          const float* __restrict__ W1,
                          const float* __restrict__ b1) {
    __shared__ float sW[2*CDIM*ODIM];
    for (int i = threadIdx.x; i < 2*CDIM*ODIM; i += blockDim.x) sW[i] = W1[i];
    __syncthreads();
    int gid = blockIdx.x * blockDim.x + threadIdx.x;   // node*64 + o
    int node = gid >> 6;
    int o = gid & 63;
    const float4* xp = (const float4*)(x + (size_t)node * CDIM);
    float xc[16];
    ((float4*)xc)[0] = xp[0];
    ((float4*)xc)[1] = xp[1];
    ((float4*)xc)[2] = xp[2];
    ((float4*)xc)[3] = xp[3];
    float u = b1[o], v = 0.f;
#pragma unroll
    for (int c = 0; c < 16; ++c) {
        float wt = sW[c*ODIM + o];
        float wb = sW[(c+16)*ODIM + o];
        u = fmaf(xc[c], wt - wb, u);
        v = fmaf(xc[c], wb, v);
    }
    g_u[gid] = u;
    g_v[gid] = v;
}

// ---------------- per-channel BN stats over all edges (deterministic) ------
__global__ void hstat_kernel() {
    int gw = (blockIdx.x * blockDim.x + threadIdx.x) >> 5;
    int l = threadIdx.x & 31;
    float s10 = 0.f, s11 = 0.f, s20 = 0.f, s21 = 0.f;
    for (int node = gw; node < TOTAL; node += NWARPS_TOT) {
        float u0 = g_u[node*ODIM + l];
        float u1 = g_u[node*ODIM + 32 + l];
        const int* ip = g_idx + node*KNN;
#pragma unroll
        for (int k = 0; k < KNN; ++k) {
            int j = ip[k];
            float v0 = g_v[j*ODIM + l];
            float v1 = g_v[j*ODIM + 32 + l];
            float h0 = u0 + v0, h1 = u1 + v1;
            s10 += h0; s20 = fmaf(h0, h0, s20);
            s11 += h1; s21 = fmaf(h1, h1, s21);
        }
    }
    __shared__ float sh1[8][64];
    __shared__ float sh2[8][64];
    int wl = threadIdx.x >> 5;
    sh1[wl][l] = s10; sh1[wl][l+32] = s11;
    sh2[wl][l] = s20; sh2[wl][l+32] = s21;
    __syncthreads();
    if (threadIdx.x < 64) {
        int ch = threadIdx.x;
        float p1 = 0.f, p2 = 0.f;
#pragma unroll
        for (int w = 0; w < 8; ++w) { p1 += sh1[w][ch]; p2 += sh2[w][ch]; }
        g_p1[blockIdx.x*ODIM + ch] = p1;
        g_p2[blockIdx.x*ODIM + ch] = p2;
    }
}

__global__ void bnfin_kernel(const float* __restrict__ g1,
                             const float* __restrict__ be1) {
    int o = threadIdx.x;
    float s1 = 0.f, s2 = 0.f;
    for (int b = 0; b < RBLOCKS; ++b) { s1 += g_p1[b*ODIM+o]; s2 += g_p2[b*ODIM+o]; }
    const float invE = 1.0f / (float)NEDGE;
    float mu  = s1 * invE;
    float var = s2 * invE - mu*mu;
    float inv = rsqrtf(var + 1e-5f);
    float A = g1[o] * inv;
    g_bnA[o] = A;
    g_bnB[o] = fmaf(-mu, A, be1[o]);
}

// ---------------- gate values per edge + gate BN stats ---------------------
__global__ void gate_kernel(const float* __restrict__ Wg,
                            const float* __restrict__ bgp) {
    int gw = (blockIdx.x*blockDim.x + threadIdx.x) >> 5;
    int l = threadIdx.x & 31;
    float A0 = g_bnA[l], B0 = g_bnB[l], A1 = g_bnA[l+32], B1 = g_bnB[l+32];
    float w0 = Wg[l], w1 = Wg[l+32];
    float bgs = bgp[0];
    float gs = 0.f, gss = 0.f;
    for (int node = gw; node < TOTAL; node += NWARPS_TOT) {
        float u0 = g_u[node*ODIM + l], u1 = g_u[node*ODIM + 32 + l];
        const int* ip = g_idx + node*KNN;
#pragma unroll
        for (int k = 0; k < KNN; ++k) {
            int j = ip[k];
            float v0 = g_v[j*ODIM + l], v1 = g_v[j*ODIM + 32 + l];
            float z0 = fmaf(u0 + v0, A0, B0);
            float z1 = fmaf(u1 + v1, A1, B1);
            float hn0 = silu_f(z0), hn1 = silu_f(z1);
            float p = fmaf(hn0, w0, hn1*w1);
#pragma unroll
            for (int off = 16; off > 0; off >>= 1)
                p += __shfl_xor_sync(0xffffffffu, p, off);
            float gt = p + bgs;
            if (l == 0) g_gt[node*KNN + k] = gt;
            gs += gt; gss = fmaf(gt, gt, gss);
        }
    }
    __shared__ float sg1[8], sg2[8];
    if (l == 0) { sg1[threadIdx.x>>5] = gs; sg2[threadIdx.x>>5] = gss; }
    __syncthreads();
    if (threadIdx.x == 0) {
        float a = 0.f, b2 = 0.f;
#pragma unroll
        for (int w = 0; w < 8; ++w) { a += sg1[w]; b2 += sg2[w]; }
        g_gp1[blockIdx.x] = a; g_gp2[blockIdx.x] = b2;
    }
}

__global__ void gfin_kernel(const float* __restrict__ gg,
                            const float* __restrict__ beg) {
    float s1 = 0.f, s2 = 0.f;
    for (int b = 0; b < RBLOCKS; ++b) { s1 += g_gp1[b]; s2 += g_gp2[b]; }
    const float invE = 1.0f / (float)NEDGE;
    float mu  = s1 * invE;
    float var = s2 * invE - mu*mu;
    float inv = rsqrtf(var + 1e-5f);
    float A = gg[0] * inv;
    g_gAB[0] = A;
    g_gAB[1] = fmaf(-mu, A, beg[0]);
}

// ---------------- softmax over K + weighted aggregation --------------------
__global__ void out_kernel(float* __restrict__ out) {
    int gw = (blockIdx.x*blockDim.x + threadIdx.x) >> 5;
    int l = threadIdx.x & 31;
    float A0 = g_bnA[l], B0 = g_bnB[l], A1 = g_bnA[l+32], B1 = g_bnB[l+32];
    float gA = g_gAB[0], gB = g_gAB[1];
    for (int node = gw; node < TOTAL; node += NWARPS_TOT) {
        float gt = (l < 16) ? g_gt[node*KNN + l] : 0.f;
        float z = fmaf(gt, gA, gB);
        float s = silu_f(z);
        float sm = (l < 16) ? s : -1e30f;
#pragma unroll
        for (int off = 16; off > 0; off >>= 1)
            sm = fmaxf(sm, __shfl_xor_sync(0xffffffffu, sm, off));
        float e = (l < 16) ? __expf(s - sm) : 0.f;
        float tot = e;
#pragma unroll
        for (int off = 16; off > 0; off >>= 1)
            tot += __shfl_xor_sync(0xffffffffu, tot, off);
        float a = e / tot;

        float u0 = g_u[node*ODIM + l], u1 = g_u[node*ODIM + 32 + l];
        float acc0 = 0.f, acc1 = 0.f;
        const int* ip = g_idx + node*KNN;
#pragma unroll
        for (int k = 0; k < KNN; ++k) {
            float ak = __shfl_sync(0xffffffffu, a, k);
            int j = ip[k];
            float v0 = g_v[j*ODIM + l], v1 = g_v[j*ODIM + 32 + l];
            float hn0 = silu_f(fmaf(u0 + v0, A0, B0));
            float hn1 = silu_f(fmaf(u1 + v1, A1, B1));
            acc0 = fmaf(ak, hn0, acc0);
            acc1 = fmaf(ak, hn1, acc1);
        }
        out[node*ODIM + l] = acc0;
        out[node*ODIM + 32 + l] = acc1;
    }
}

// ---------------- launch ----------------------------------------------------
extern "C" void kernel_launch(void* const* d_in, const int* in_sizes, int n_in,
                              void* d_out, int out_size) {
    const float* x   = (const float*)d_in[0];
    // d_in[1] = batch (sorted equal-size graphs; unused)
    const float* W1  = (const float*)d_in[2];
    const float* b1  = (const float*)d_in[3];
    const float* g1  = (const float*)d_in[4];
    const float* be1 = (const float*)d_in[5];
    const float* Wg  = (const float*)d_in[6];
    const float* bg  = (const float*)d_in[7];
    const float* gg  = (const float*)d_in[8];
    const float* beg = (const float*)d_in[9];
    float* out = (float*)d_out;

    const int knn_smem = NPG*CDIM*4 + NPG*4 + 256*KNN*8;  // 172032 B
    cudaFuncSetAttribute(knn_kernel, cudaFuncAttributeMaxDynamicSharedMemorySize, knn_smem);

    knn_kernel<<<BGRAPH*(NPG/256), 256, knn_smem>>>(x);
    uv_kernel<<<(TOTAL*ODIM)/256, 256>>>(x, W1, b1);
    hstat_kernel<<<RBLOCKS, RTHREADS>>>();
    bnfin_kernel<<<1, 64>>>(g1, be1);
    gate_kernel<<<RBLOCKS, RTHREADS>>>(Wg, bg);
    gfin_kernel<<<1, 1>>>(gg, beg);
    out_kernel<<<RBLOCKS, RTHREADS>>>(out);
}

// round 2
// speedup vs baseline: 1.0515x; 1.0515x over previous
#include <cuda_runtime.h>

// ---------------- problem constants (fixed by setup_inputs) ----------------
#define TOTAL   32768          // B*N nodes
#define BGRAPH  16
#define NPG     2048           // nodes per graph
#define CDIM    16
#define ODIM    64
#define KNN     16
#define NEDGE   (TOTAL*KNN)    // 524288
#define RBLOCKS 512
#define RTHREADS 256
#define NWARPS_TOT (RBLOCKS*(RTHREADS/32))   // 4096 warps -> 8 nodes/warp

// ---------------- device scratch (static, allocation-free) -----------------
__device__ float g_u[TOTAL*ODIM];
__device__ float g_v[TOTAL*ODIM];
__device__ int   g_idx[NEDGE];
__device__ float g_gt[NEDGE];
__device__ float g_p1[RBLOCKS*ODIM];
__device__ float g_p2[RBLOCKS*ODIM];
__device__ float g_gp1[RBLOCKS];
__device__ float g_gp2[RBLOCKS];
__device__ float g_bnA[ODIM];
__device__ float g_bnB[ODIM];
__device__ float g_gAB[2];

__device__ __forceinline__ float silu_f(float z) {
    return z / (1.0f + __expf(-z));
}

// ---------------- kNN: thread-per-query, buffered replace-max top-16 -------
__device__ __forceinline__ void knn_flush(float (&bk)[KNN], int (&bjv)[KNN],
                                          float &cmax, int &cnt,
                                          const unsigned long long* sbuf) {
    unsigned mx = __reduce_max_sync(0xffffffffu, (unsigned)cnt);
    for (unsigned t = 0; t < mx; ++t) {
        bool act = (t < (unsigned)cnt);
        unsigned long long pk = act ? sbuf[t*256u + threadIdx.x] : 0ull;
        float key = __uint_as_float((unsigned)(pk >> 32));
        int jj = (int)(pk & 0xffffffffu);
        if (act && key < cmax) {
            int pmax = 0; float vmax = bk[0];
#pragma unroll
            for (int p = 1; p < KNN; ++p) { if (bk[p] > vmax) { vmax = bk[p]; pmax = p; } }
#pragma unroll
            for (int p = 0; p < KNN; ++p) { if (p == pmax) { bk[p] = key; bjv[p] = jj; } }
            cmax = bk[0];
#pragma unroll
            for (int p = 1; p < KNN; ++p) cmax = fmaxf(cmax, bk[p]);
        }
    }
    cnt = 0;
}

__global__ void __launch_bounds__(256, 1) knn_kernel(const float* __restrict__ x) {
    extern __shared__ unsigned char smraw[];
    float4* sp4 = (float4*)smraw;                                   // 2048*4 float4 (131072 B)
    float*  ssq = (float*)(smraw + NPG*CDIM*4);                     // 2048 floats (8192 B)
    unsigned long long* sbuf =
        (unsigned long long*)(smraw + NPG*CDIM*4 + NPG*4);          // 16*256 u64 (32768 B)

    int g = blockIdx.x >> 3;   // 8 blocks per graph
    const float* xg = x + (size_t)g * (NPG*CDIM);

    for (int t = threadIdx.x; t < NPG; t += 256) {
        const float4* p = (const float4*)(xg + t*CDIM);
        float4 f0 = p[0], f1 = p[1], f2 = p[2], f3 = p[3];
        sp4[t*4+0] = f0; sp4[t*4+1] = f1; sp4[t*4+2] = f2; sp4[t*4+3] = f3;
        float sq = f0.x*f0.x + f0.y*f0.y + f0.z*f0.z + f0.w*f0.w
                 + f1.x*f1.x + f1.y*f1.y + f1.z*f1.z + f1.w*f1.w
                 + f2.x*f2.x + f2.y*f2.y + f2.z*f2.z + f2.w*f2.w
                 + f3.x*f3.x + f3.y*f3.y + f3.z*f3.z + f3.w*f3.w;
        ssq[t] = sq;
    }
    __syncthreads();

    int qloc = ((blockIdx.x & 7) << 8) + threadIdx.x;
    float xq[16];
    ((float4*)xq)[0] = sp4[qloc*4+0];
    ((float4*)xq)[1] = sp4[qloc*4+1];
    ((float4*)xq)[2] = sp4[qloc*4+2];
    ((float4*)xq)[3] = sp4[qloc*4+3];
#pragma unroll
    for (int c = 0; c < 16; ++c) xq[c] *= -2.0f;   // key = sq_j - 2*dot

    float bk[KNN]; int bjv[KNN];
#pragma unroll
    for (int p = 0; p < KNN; ++p) { bk[p] = __int_as_float(0x7f800000); bjv[p] = 0; }
    float cmax = __int_as_float(0x7f800000);
    int cnt = 0;

    for (int j = 0; j < NPG; ++j) {
        float4 c0 = sp4[j*4+0], c1 = sp4[j*4+1], c2 = sp4[j*4+2], c3 = sp4[j*4+3];
        float k0 = ssq[j];
        k0 = fmaf(xq[0],  c0.x, k0); k0 = fmaf(xq[1],  c0.y, k0);
        k0 = fmaf(xq[2],  c0.z, k0); k0 = fmaf(xq[3],  c0.w, k0);
        float k1 =        xq[4]*c1.x;
        k1 = fmaf(xq[5],  c1.y, k1); k1 = fmaf(xq[6],  c1.z, k1); k1 = fmaf(xq[7],  c1.w, k1);
        float k2 =        xq[8]*c2.x;
        k2 = fmaf(xq[9],  c2.y, k2); k2 = fmaf(xq[10], c2.z, k2); k2 = fmaf(xq[11], c2.w, k2);
        float k3 =        xq[12]*c3.x;
        k3 = fmaf(xq[13], c3.y, k3); k3 = fmaf(xq[14], c3.z, k3); k3 = fmaf(xq[15], c3.w, k3);
        float key = (k0 + k1) + (k2 + k3);

        if (key < cmax) {
            sbuf[(unsigned)cnt*256u + threadIdx.x] =
                (((unsigned long long)__float_as_uint(key)) << 32) | (unsigned)j;
            ++cnt;
        }
        if (__any_sync(0xffffffffu, cnt == KNN)) {
            knn_flush(bk, bjv, cmax, cnt, sbuf);
        }
    }
    knn_flush(bk, bjv, cmax, cnt, sbuf);

    int base = (g*NPG + qloc) * KNN;
    int goff = g * NPG;
#pragma unroll
    for (int p = 0; p < KNN; ++p) g_idx[base + p] = goff + bjv[p];
}

// ---------------- u/v per node: h_edge = u_i + v_j -------------------------
__global__ void uv_kernel(const float* __restrict__ x,
                          const float* __restrict__ W1,
                          const float* __restrict__ b1) {
    __shared__ float sW[2*CDIM*ODIM];
    for (int i = threadIdx.x; i < 2*CDIM*ODIM; i += blockDim.x) sW[i] = W1[i];
    __syncthreads();
    int gid = blockIdx.x * blockDim.x + threadIdx.x;   // node*64 + o
    int node = gid >> 6;
    int o = gid & 63;
    const float4* xp = (const float4*)(x + (size_t)node * CDIM);
    float xc[16];
    ((float4*)xc)[0] = xp[0];
    ((float4*)xc)[1] = xp[1];
    ((float4*)xc)[2] = xp[2];
    ((float4*)xc)[3] = xp[3];
    float u = b1[o], v = 0.f;
#pragma unroll
    for (int c = 0; c < 16; ++c) {
        float wt = sW[c*ODIM + o];
        float wb = sW[(c+16)*ODIM + o];
        u = fmaf(xc[c], wt - wb, u);
        v = fmaf(xc[c], wb, v);
    }
    g_u[gid] = u;
    g_v[gid] = v;
}

// ---------------- per-channel BN stats over all edges (deterministic) ------
__global__ void hstat_kernel() {
    int gw = (blockIdx.x * blockDim.x + threadIdx.x) >> 5;
    int l = threadIdx.x & 31;
    float s10 = 0.f, s11 = 0.f, s20 = 0.f, s21 = 0.f;
    for (int node = gw; node < TOTAL; node += NWARPS_TOT) {
        float u0 = g_u[node*ODIM + l];
        float u1 = g_u[node*ODIM + 32 + l];
        const int* ip = g_idx + node*KNN;
#pragma unroll
        for (int k = 0; k < KNN; ++k) {
            int j = ip[k];
            float v0 = g_v[j*ODIM + l];
            float v1 = g_v[j*ODIM + 32 + l];
            float h0 = u0 + v0, h1 = u1 + v1;
            s10 += h0; s20 = fmaf(h0, h0, s20);
            s11 += h1; s21 = fmaf(h1, h1, s21);
        }
    }
    __shared__ float sh1[8][64];
    __shared__ float sh2[8][64];
    int wl = threadIdx.x >> 5;
    sh1[wl][l] = s10; sh1[wl][l+32] = s11;
    sh2[wl][l] = s20; sh2[wl][l+32] = s21;
    __syncthreads();
    if (threadIdx.x < 64) {
        int ch = threadIdx.x;
        float p1 = 0.f, p2 = 0.f;
#pragma unroll
        for (int w = 0; w < 8; ++w) { p1 += sh1[w][ch]; p2 += sh2[w][ch]; }
        g_p1[blockIdx.x*ODIM + ch] = p1;
        g_p2[blockIdx.x*ODIM + ch] = p2;
    }
}

// ---------------- BN finalize: 512 threads, 8 groups x 64 channels ---------
__global__ void __launch_bounds__(512) bnfin_kernel(const float* __restrict__ g1,
                                                    const float* __restrict__ be1) {
    int o   = threadIdx.x & 63;
    int grp = threadIdx.x >> 6;   // 0..7
    float s1 = 0.f, s2 = 0.f;
    for (int b = grp; b < RBLOCKS; b += 8) {
        s1 += g_p1[b*ODIM + o];
        s2 += g_p2[b*ODIM + o];
    }
    __shared__ float sh1[8][64];
    __shared__ float sh2[8][64];
    sh1[grp][o] = s1; sh2[grp][o] = s2;
    __syncthreads();
    if (threadIdx.x < 64) {
        float p1 = 0.f, p2 = 0.f;
#pragma unroll
        for (int w = 0; w < 8; ++w) { p1 += sh1[w][threadIdx.x]; p2 += sh2[w][threadIdx.x]; }
        const float invE = 1.0f / (float)NEDGE;
        float mu  = p1 * invE;
        float var = p2 * invE - mu*mu;
        float inv = rsqrtf(var + 1e-5f);
        float A = g1[threadIdx.x] * inv;
        g_bnA[threadIdx.x] = A;
        g_bnB[threadIdx.x] = fmaf(-mu, A, be1[threadIdx.x]);
    }
}

// ---------------- gate values per edge + gate BN stats ---------------------
__global__ void gate_kernel(const float* __restrict__ Wg,
                            const float* __restrict__ bgp) {
    int gw = (blockIdx.x*blockDim.x + threadIdx.x) >> 5;
    int l = threadIdx.x & 31;
    float A0 = g_bnA[l], B0 = g_bnB[l], A1 = g_bnA[l+32], B1 = g_bnB[l+32];
    float w0 = Wg[l], w1 = Wg[l+32];
    float bgs = bgp[0];
    float gs = 0.f, gss = 0.f;
    for (int node = gw; node < TOTAL; node += NWARPS_TOT) {
        float u0 = g_u[node*ODIM + l], u1 = g_u[node*ODIM + 32 + l];
        const int* ip = g_idx + node*KNN;
#pragma unroll
        for (int k = 0; k < KNN; ++k) {
            int j = ip[k];
            float v0 = g_v[j*ODIM + l], v1 = g_v[j*ODIM + 32 + l];
            float z0 = fmaf(u0 + v0, A0, B0);
            float z1 = fmaf(u1 + v1, A1, B1);
            float hn0 = silu_f(z0), hn1 = silu_f(z1);
            float p = fmaf(hn0, w0, hn1*w1);
#pragma unroll
            for (int off = 16; off > 0; off >>= 1)
                p += __shfl_xor_sync(0xffffffffu, p, off);
            float gt = p + bgs;
            if (l == 0) g_gt[node*KNN + k] = gt;
            gs += gt; gss = fmaf(gt, gt, gss);
        }
    }
    __shared__ float sg1[8], sg2[8];
    if (l == 0) { sg1[threadIdx.x>>5] = gs; sg2[threadIdx.x>>5] = gss; }
    __syncthreads();
    if (threadIdx.x == 0) {
        float a = 0.f, b2 = 0.f;
#pragma unroll
        for (int w = 0; w < 8; ++w) { a += sg1[w]; b2 += sg2[w]; }
        g_gp1[blockIdx.x] = a; g_gp2[blockIdx.x] = b2;
    }
}

// ---------------- gate finalize: 512 threads, full parallel reduce ---------
__global__ void __launch_bounds__(512) gfin_kernel(const float* __restrict__ gg,
                                                   const float* __restrict__ beg) {
    int t = threadIdx.x;           // one partial per thread (RBLOCKS == 512)
    float a  = g_gp1[t];
    float b2 = g_gp2[t];
#pragma unroll
    for (int off = 16; off > 0; off >>= 1) {
        a  += __shfl_xor_sync(0xffffffffu, a,  off);
        b2 += __shfl_xor_sync(0xffffffffu, b2, off);
    }
    __shared__ float sa[16], sb[16];
    int wid = t >> 5;
    if ((t & 31) == 0) { sa[wid] = a; sb[wid] = b2; }
    __syncthreads();
    if (t == 0) {
        float s1 = 0.f, s2 = 0.f;
#pragma unroll
        for (int w = 0; w < 16; ++w) { s1 += sa[w]; s2 += sb[w]; }
        const float invE = 1.0f / (float)NEDGE;
        float mu  = s1 * invE;
        float var = s2 * invE - mu*mu;
        float inv = rsqrtf(var + 1e-5f);
        float A = gg[0] * inv;
        g_gAB[0] = A;
        g_gAB[1] = fmaf(-mu, A, beg[0]);
    }
}

// ---------------- softmax over K + weighted aggregation --------------------
__global__ void out_kernel(float* __restrict__ out) {
    int gw = (blockIdx.x*blockDim.x + threadIdx.x) >> 5;
    int l = threadIdx.x & 31;
    float A0 = g_bnA[l], B0 = g_bnB[l], A1 = g_bnA[l+32], B1 = g_bnB[l+32];
    float gA = g_gAB[0], gB = g_gAB[1];
    for (int node = gw; node < TOTAL; node += NWARPS_TOT) {
        float gt = (l < 16) ? g_gt[node*KNN + l] : 0.f;
        float z = fmaf(gt, gA, gB);
        float s = silu_f(z);
        float sm = (l < 16) ? s : -1e30f;
#pragma unroll
        for (int off = 16; off > 0; off >>= 1)
            sm = fmaxf(sm, __shfl_xor_sync(0xffffffffu, sm, off));
        float e = (l < 16) ? __expf(s - sm) : 0.f;
        float tot = e;
#pragma unroll
        for (int off = 16; off > 0; off >>= 1)
            tot += __shfl_xor_sync(0xffffffffu, tot, off);
        float a = e / tot;

        float u0 = g_u[node*ODIM + l], u1 = g_u[node*ODIM + 32 + l];
        float acc0 = 0.f, acc1 = 0.f;
        const int* ip = g_idx + node*KNN;
#pragma unroll
        for (int k = 0; k < KNN; ++k) {
            float ak = __shfl_sync(0xffffffffu, a, k);
            int j = ip[k];
            float v0 = g_v[j*ODIM + l], v1 = g_v[j*ODIM + 32 + l];
            float hn0 = silu_f(fmaf(u0 + v0, A0, B0));
            float hn1 = silu_f(fmaf(u1 + v1, A1, B1));
            acc0 = fmaf(ak, hn0, acc0);
            acc1 = fmaf(ak, hn1, acc1);
        }
        out[node*ODIM + l] = acc0;
        out[node*ODIM + 32 + l] = acc1;
    }
}

// ---------------- launch ----------------------------------------------------
extern "C" void kernel_launch(void* const* d_in, const int* in_sizes, int n_in,
                              void* d_out, int out_size) {
    const float* x   = (const float*)d_in[0];
    // d_in[1] = batch (sorted equal-size graphs; unused)
    const float* W1  = (const float*)d_in[2];
    const float* b1  = (const float*)d_in[3];
    const float* g1  = (const float*)d_in[4];
    const float* be1 = (const float*)d_in[5];
    const float* Wg  = (const float*)d_in[6];
    const float* bg  = (const float*)d_in[7];
    const float* gg  = (const float*)d_in[8];
    const float* beg = (const float*)d_in[9];
    float* out = (float*)d_out;

    const int knn_smem = NPG*CDIM*4 + NPG*4 + 256*KNN*8;  // 172032 B
    cudaFuncSetAttribute(knn_kernel, cudaFuncAttributeMaxDynamicSharedMemorySize, knn_smem);

    knn_kernel<<<BGRAPH*(NPG/256), 256, knn_smem>>>(x);
    uv_kernel<<<(TOTAL*ODIM)/256, 256>>>(x, W1, b1);
    hstat_kernel<<<RBLOCKS, RTHREADS>>>();
    bnfin_kernel<<<1, 512>>>(g1, be1);
    gate_kernel<<<RBLOCKS, RTHREADS>>>(Wg, bg);
    gfin_kernel<<<1, 512>>>(gg, beg);
    out_kernel<<<RBLOCKS, RTHREADS>>>(out);
}